// round 13
// baseline (speedup 1.0000x reference)
#include <cuda_runtime.h>

#define NN        1024
#define TOTAL_AB  4092
#define WPC       4                 // warps (rows) per CTA
#define ROWPAD    (NN + (NN >> 5))  // skewed plane size (1056 elements)

typedef unsigned long long u64;

__device__ __forceinline__ int skew(int i) { return i + (i >> 5); }
__device__ __forceinline__ float sigmoidf_(float z) { return 1.0f / (1.0f + expf(-z)); }

// ===================== f32x2 packed helpers (PTX-only) =======================
__device__ __forceinline__ u64 pk2(float x, float y) {
    u64 r; asm("mov.b64 %0,{%1,%2};" : "=l"(r) : "f"(x), "f"(y)); return r;
}
__device__ __forceinline__ float2 upk2(u64 v) {
    float2 r; asm("mov.b64 {%0,%1},%2;" : "=f"(r.x), "=f"(r.y) : "l"(v)); return r;
}
__device__ __forceinline__ u64 dup2(float x) { return pk2(x, x); }
__device__ __forceinline__ u64 swp2(u64 v) {
    u64 r;
    asm("{.reg .f32 a,b; mov.b64 {a,b},%1; mov.b64 %0,{b,a};}" : "=l"(r) : "l"(v));
    return r;
}
__device__ __forceinline__ u64 fma2_(u64 a, u64 b, u64 c) {
    u64 d; asm("fma.rn.f32x2 %0,%1,%2,%3;" : "=l"(d) : "l"(a), "l"(b), "l"(c)); return d;
}
__device__ __forceinline__ u64 mul2_(u64 a, u64 b) {
    u64 d; asm("mul.rn.f32x2 %0,%1,%2;" : "=l"(d) : "l"(a), "l"(b)); return d;
}
__device__ __forceinline__ u64 lerp2(u64 q, u64 x, u64 p, u64 e) {
    return fma2_(q, x, mul2_(p, e));
}

// ====== repacked large-diag coefficient buffers (filled by prep kernel) ======
// pair-unit offsets within a depth: m=64:0, 128:32, 256:96, 512:224, 1024:480
__device__ float4 g_AB[2][992];
__device__ float4 g_CD[2][992];

__global__ void prep_kernel(const float* __restrict__ abcd_f) {
    int t = blockIdx.x * blockDim.x + threadIdx.x;
    if (t >= 2 * 992) return;
    int d = t / 992, r = t % 992;
    int m, k, off, po;
    if      (r < 32)  { m = 64;   k = r;       off = 3840; po = 0;   }
    else if (r < 96)  { m = 128;  k = r - 32;  off = 3584; po = 32;  }
    else if (r < 224) { m = 256;  k = r - 96;  off = 3072; po = 96;  }
    else if (r < 480) { m = 512;  k = r - 224; off = 2048; po = 224; }
    else              { m = 1024; k = r - 480; off = 0;    po = 480; }
    const float2* ab = reinterpret_cast<const float2*>(abcd_f) + d * TOTAL_AB + off;
    float2 A = ab[k], B = ab[m / 2 + k], C = ab[m + k], D = ab[m + m / 2 + k];
    g_AB[d][po + k] = make_float4(A.x, A.y, B.x, B.y);
    g_CD[d][po + k] = make_float4(C.x, C.y, D.x, D.y);
}

// ================= small (in-register) perm factor, REAL, M = 4..32 ==========
template<int M>
__device__ __forceinline__ void perm_small_r(float (&v)[32], float p0, float p1, float p2) {
    const float q0 = 1.0f - p0, q1 = 1.0f - p1, q2 = 1.0f - p2;
#pragma unroll
    for (int jb = 0; jb < 32; jb += M) {
        float todd[M / 2];
#pragma unroll
        for (int k = 0; k < M / 2; ++k) todd[k] = v[jb + 2 * k + 1];
#pragma unroll
        for (int k = 0; k < M / 2; ++k)
            v[jb + k] = q0 * v[jb + k] + p0 * v[jb + 2 * k];
#pragma unroll
        for (int k = 0; k < M / 2; ++k)
            v[jb + M / 2 + k] = q0 * v[jb + M / 2 + k] + p0 * todd[k];
#pragma unroll
        for (int k = 0; k < M / 4; ++k) {
            int a = jb + k, b = jb + M / 2 - 1 - k;
            float va = v[a], vb = v[b];
            v[a] = q1 * va + p1 * vb;  v[b] = q1 * vb + p1 * va;
            int c = jb + M / 2 + k, e = jb + M - 1 - k;
            float vc = v[c], ve = v[e];
            v[c] = q2 * vc + p2 * ve;  v[e] = q2 * ve + p2 * vc;
        }
    }
}

// ============ small perm factor, COMPLEX packed (contiguous layout) ==========
template<int M>
__device__ __forceinline__ void perm_small_p(u64 (&v)[32], u64 q02, u64 p02,
                                             u64 q12, u64 p12, u64 q22, u64 p22) {
#pragma unroll
    for (int jb = 0; jb < 32; jb += M) {
        u64 todd[M / 2];
#pragma unroll
        for (int k = 0; k < M / 2; ++k) todd[k] = v[jb + 2 * k + 1];
#pragma unroll
        for (int k = 0; k < M / 2; ++k)
            v[jb + k] = lerp2(q02, v[jb + k], p02, v[jb + 2 * k]);
#pragma unroll
        for (int k = 0; k < M / 2; ++k)
            v[jb + M / 2 + k] = lerp2(q02, v[jb + M / 2 + k], p02, todd[k]);
#pragma unroll
        for (int k = 0; k < M / 4; ++k) {
            int a = jb + k, b = jb + M / 2 - 1 - k;
            u64 va = v[a], vb = v[b];
            v[a] = lerp2(q12, va, p12, vb);
            v[b] = lerp2(q12, vb, p12, va);
            int c = jb + M / 2 + k, e = jb + M - 1 - k;
            u64 vc = v[c], ve = v[e];
            v[c] = lerp2(q22, vc, p22, ve);
            v[e] = lerp2(q22, ve, p22, vc);
        }
    }
}

// ============ large perm factor, REAL, strided layout (lane + 32*j) ==========
template<int M, bool FIRST>
__device__ __forceinline__ void perm_large_r(float (&v)[32], float* __restrict__ sr,
                                             int lane, float p0, float p1, float p2) {
    constexpr int M32 = M / 32, H32 = M / 64;
    const float q0 = 1.0f - p0;
    __syncwarp();
    if (FIRST) {
#pragma unroll
        for (int j = 0; j < 32; ++j) sr[skew(32 * lane + j)] = v[j];
    } else {
#pragma unroll
        for (int j = 0; j < 32; ++j) sr[skew(lane + 32 * j)] = v[j];
    }
    __syncwarp();
#pragma unroll
    for (int j = 0; j < 32; ++j) {
        int jm = j & (M32 - 1);
        bool hieo = jm >= H32;
        int i = lane + 32 * j;
        int q = i & (M - 1);
        int src = i + q - (hieo ? (M - 1) : 0);
        float xi = FIRST ? sr[skew(i)] : v[j];
        v[j] = q0 * xi + p0 * sr[skew(src)];
    }
    const int rl = 31 - lane;
#pragma unroll
    for (int j = 0; j < 32; ++j) {
        int jm = j & (M32 - 1);
        bool hi = jm >= H32;
        int j2 = j - 2 * jm + (hi ? 2 * H32 : 0) + H32 - 1;
        float pp = hi ? p2 : p1;
        float qq = 1.0f - pp;
        if (j2 == j) {
            float a = __shfl_sync(0xffffffffu, v[j], rl);
            v[j] = qq * v[j] + pp * a;
        } else if (j2 > j) {
            float a = __shfl_sync(0xffffffffu, v[j2], rl);
            float b = __shfl_sync(0xffffffffu, v[j],  rl);
            v[j]  = qq * v[j]  + pp * a;
            v[j2] = qq * v[j2] + pp * b;
        }
    }
}

// ===== large perm factor, COMPLEX packed, strided layout, u64 smem plane =====
// non-FIRST: eo via INVERSE-SCATTER store (element stored at its eo destination
// = two contiguous 16-u64 runs, low-conflict), then conflict-free reload of own
// strided slot.  FIRST: gather form (also performs contiguous->strided change).
template<int M, bool FIRST>
__device__ __forceinline__ void perm_large_p(u64 (&v)[32], u64* __restrict__ sp, int lane,
                                             u64 q02, u64 p02, u64 q12, u64 p12,
                                             u64 q22, u64 p22) {
    constexpr int M32 = M / 32, H32 = M / 64, HS = M / 2;
    __syncwarp();
    if (FIRST) {
#pragma unroll
        for (int j = 0; j < 32; ++j) sp[skew(32 * lane + j)] = v[j];
        __syncwarp();
#pragma unroll
        for (int j = 0; j < 32; ++j) {
            int jm = j & (M32 - 1);
            bool hieo = jm >= H32;
            int i = lane + 32 * j;
            int q = i & (M - 1);
            int src = i + q - (hieo ? (M - 1) : 0);
            u64 x = sp[skew(i)];
            v[j] = lerp2(q02, x, p02, sp[skew(src)]);
        }
    } else {
        // scatter: element at block-position q goes to eo destination
        // dst = base + (q>>1) + (q odd ? HS : 0);  q parity == lane parity
#pragma unroll
        for (int j = 0; j < 32; ++j) {
            int jm = j & (M32 - 1);
            int i = lane + 32 * j;
            int q = lane + 32 * jm;              // i & (M-1)
            int dst = (i - q) + (q >> 1) + ((lane & 1) ? HS : 0);
            sp[skew(dst)] = v[j];
        }
        __syncwarp();
#pragma unroll
        for (int j = 0; j < 32; ++j) {
            int i = lane + 32 * j;
            v[j] = lerp2(q02, v[j], p02, sp[skew(i)]);
        }
    }
    const int rl = 31 - lane;
#pragma unroll
    for (int j = 0; j < 32; ++j) {
        int jm = j & (M32 - 1);
        bool hi = jm >= H32;
        int j2 = j - 2 * jm + (hi ? 2 * H32 : 0) + H32 - 1;
        u64 pp2 = hi ? p22 : p12;
        u64 qq2 = hi ? q22 : q12;
        if (j2 == j) {
            u64 a = __shfl_sync(0xffffffffu, v[j], rl);
            v[j] = lerp2(qq2, v[j], pp2, a);
        } else if (j2 > j) {
            u64 a = __shfl_sync(0xffffffffu, v[j2], rl);
            u64 b = __shfl_sync(0xffffffffu, v[j],  rl);
            v[j]  = lerp2(qq2, v[j],  pp2, a);
            v[j2] = lerp2(qq2, v[j2], pp2, b);
        }
    }
}

// ====== small diag, COMPLEX packed, contiguous; coeffs via LDS.128 ===========
// dup[k][8] = {(Ax,Ax),(-Ay,Ay),(Bx,Bx),(-By,By),(Cx,Cx),(-Cy,Cy),(Dx,Dx),(-Dy,Dy)}
template<int M>
__device__ __forceinline__ void diag_small_p(u64 (&v)[32], const u64 (*__restrict__ dup)[8]) {
#pragma unroll
    for (int k = 0; k < M / 2; ++k) {
        const ulonglong2* __restrict__ q = reinterpret_cast<const ulonglong2*>(dup[k]);
        const ulonglong2 t0 = q[0], t1 = q[1], t2 = q[2], t3 = q[3];
        const u64 Ax = t0.x, Ay = t0.y, Bx = t1.x, By = t1.y;
        const u64 Cx = t2.x, Cy = t2.y, Dx = t3.x, Dy = t3.y;
#pragma unroll
        for (int jb = 0; jb < 32; jb += M) {
            u64 x1 = v[jb + k], x2 = v[jb + k + M / 2];
            u64 x1s = swp2(x1), x2s = swp2(x2);
            v[jb + k]         = fma2_(Ax, x1, fma2_(Ay, x1s, fma2_(Bx, x2, mul2_(By, x2s))));
            v[jb + k + M / 2] = fma2_(Cx, x1, fma2_(Cy, x1s, fma2_(Dx, x2, mul2_(Dy, x2s))));
        }
    }
}

// ====== large diag, strided layout, repacked float4 coeffs (2x LDG.128) ======
template<int M>
__device__ __forceinline__ void diag_large_g(u64 (&v)[32],
                                             const float4* __restrict__ gab,
                                             const float4* __restrict__ gcd, int lane) {
    constexpr int M32 = M / 32, H32 = M / 64;
#pragma unroll
    for (int j = 0; j < 32; ++j) {
        int jm = j & (M32 - 1);
        if (jm < H32) {
            int j2 = j + H32;
            int k = lane + 32 * jm;            // consecutive across lanes
            float4 AB = gab[k];
            float4 CD = gcd[k];
            float2 x1 = upk2(v[j]), x2 = upk2(v[j2]);
            float yr1 = AB.x * x1.x - AB.y * x1.y + AB.z * x2.x - AB.w * x2.y;
            float yi1 = AB.x * x1.y + AB.y * x1.x + AB.z * x2.y + AB.w * x2.x;
            float yr2 = CD.x * x1.x - CD.y * x1.y + CD.z * x2.x - CD.w * x2.y;
            float yi2 = CD.x * x1.y + CD.y * x1.x + CD.z * x2.y + CD.w * x2.x;
            v[j]  = pk2(yr1, yi1);
            v[j2] = pk2(yr2, yi2);
        }
    }
}

// ============================ layout transposes ==============================
__device__ __forceinline__ void tr_s2c_r(float (&v)[32], float* __restrict__ sr, int lane) {
    __syncwarp();
#pragma unroll
    for (int j = 0; j < 32; ++j) sr[skew(lane + 32 * j)] = v[j];
    __syncwarp();
#pragma unroll
    for (int j = 0; j < 32; ++j) v[j] = sr[skew(32 * lane + j)];
}
__device__ __forceinline__ void tr_s2c_p(u64 (&v)[32], u64* __restrict__ sp, int lane) {
    __syncwarp();
#pragma unroll
    for (int j = 0; j < 32; ++j) sp[skew(lane + 32 * j)] = v[j];
    __syncwarp();
#pragma unroll
    for (int j = 0; j < 32; ++j) v[j] = sp[skew(32 * lane + j)];
}
__device__ __forceinline__ void tr_c2s_p(u64 (&v)[32], u64* __restrict__ sp, int lane) {
    __syncwarp();
#pragma unroll
    for (int j = 0; j < 32; ++j) sp[skew(32 * lane + j)] = v[j];
    __syncwarp();
#pragma unroll
    for (int j = 0; j < 32; ++j) v[j] = sp[skew(lane + 32 * j)];
}

__global__ void __launch_bounds__(WPC * 32, 3)
butterfly_kernel(const float* __restrict__ x,
                 const float* __restrict__ perm_logit,
                 const float* __restrict__ abcd_f,
                 const float* __restrict__ bias,
                 float* __restrict__ out)
{
    __shared__ u64 splane[WPC][ROWPAD];                 // 33.8 KB per-warp row plane
    __shared__ __align__(16) u64 sdup[2][31][8];        // 3.9 KB packed small-diag coeffs

    const int warp = threadIdx.x >> 5;
    const int lane = threadIdx.x & 31;
    const int row  = blockIdx.x * WPC + warp;
    u64*   sp  = splane[warp];
    float* srf = reinterpret_cast<float*>(sp);          // float view for real sections

    const float2* abcd = reinterpret_cast<const float2*>(abcd_f);

    // ---- build packed coefficient table for small diags (both depths) ----
    for (int t = threadIdx.x; t < 62; t += blockDim.x) {
        int d = t / 31, s = t % 31;
        int M, k, fac;
        if      (s < 1)  { M = 2;  k = s;      fac = 4088; }
        else if (s < 3)  { M = 4;  k = s - 1;  fac = 4080; }
        else if (s < 7)  { M = 8;  k = s - 3;  fac = 4064; }
        else if (s < 15) { M = 16; k = s - 7;  fac = 4032; }
        else             { M = 32; k = s - 15; fac = 3968; }
        const float2* ab = abcd + d * TOTAL_AB + fac;
        float2 A = ab[k], B = ab[M / 2 + k], C = ab[M + k], D = ab[M + M / 2 + k];
        ulonglong2* o = reinterpret_cast<ulonglong2*>(sdup[d][s]);
        o[0] = make_ulonglong2(dup2(A.x), pk2(-A.y, A.y));
        o[1] = make_ulonglong2(dup2(B.x), pk2(-B.y, B.y));
        o[2] = make_ulonglong2(dup2(C.x), pk2(-C.y, C.y));
        o[3] = make_ulonglong2(dup2(D.x), pk2(-D.y, D.y));
    }
    __syncthreads();

    // ---- coalesced load of the row (real) into smem, pick up contiguous chunk ----
    const float* xr = x + (size_t)row * NN;
#pragma unroll
    for (int it = 0; it < 8; ++it) {
        int p = it * 128 + lane * 4;
        float4 t = *reinterpret_cast<const float4*>(xr + p);
        srf[skew(p + 0)] = t.x;
        srf[skew(p + 1)] = t.y;
        srf[skew(p + 2)] = t.z;
        srf[skew(p + 3)] = t.w;
    }
    __syncwarp();
    float vr[32];
#pragma unroll
    for (int j = 0; j < 32; ++j) vr[j] = srf[skew(lane * 32 + j)];

    // ======================= depth 0: perms are purely REAL ===================
    {
        const float p0 = sigmoidf_(perm_logit[0]);
        const float p1 = sigmoidf_(perm_logit[1]);
        const float p2 = sigmoidf_(perm_logit[2]);
        perm_small_r<4 >(vr, p0, p1, p2);
        perm_small_r<8 >(vr, p0, p1, p2);
        perm_small_r<16>(vr, p0, p1, p2);
        perm_small_r<32>(vr, p0, p1, p2);
        perm_large_r<64,   true >(vr, srf, lane, p0, p1, p2);
        perm_large_r<128,  false>(vr, srf, lane, p0, p1, p2);
        perm_large_r<256,  false>(vr, srf, lane, p0, p1, p2);
        perm_large_r<512,  false>(vr, srf, lane, p0, p1, p2);
        perm_large_r<1024, false>(vr, srf, lane, p0, p1, p2);
        tr_s2c_r(vr, srf, lane);   // back to contiguous for diags
    }

    // ---- first diag (m=2) with imag==0 input: real -> packed complex ----
    u64 vc[32];
    {
        const u64* abq = reinterpret_cast<const u64*>(abcd + 4088);
        const u64 A = abq[0], B = abq[1], C = abq[2], D = abq[3];
#pragma unroll
        for (int jb = 0; jb < 32; jb += 2) {
            u64 x1 = dup2(vr[jb]), x2 = dup2(vr[jb + 1]);
            vc[jb]     = fma2_(A, x1, mul2_(B, x2));
            vc[jb + 1] = fma2_(C, x1, mul2_(D, x2));
        }
    }
    diag_small_p<4 >(vc, sdup[0] + 1);
    diag_small_p<8 >(vc, sdup[0] + 3);
    diag_small_p<16>(vc, sdup[0] + 7);
    diag_small_p<32>(vc, sdup[0] + 15);
    tr_c2s_p(vc, sp, lane);               // strided for large diags
    diag_large_g<64  >(vc, g_AB[0] + 0,   g_CD[0] + 0,   lane);
    diag_large_g<128 >(vc, g_AB[0] + 32,  g_CD[0] + 32,  lane);
    diag_large_g<256 >(vc, g_AB[0] + 96,  g_CD[0] + 96,  lane);
    diag_large_g<512 >(vc, g_AB[0] + 224, g_CD[0] + 224, lane);
    diag_large_g<1024>(vc, g_AB[0] + 480, g_CD[0] + 480, lane);

    // ======================= depth 1: full packed complex =====================
    {
        const float p0 = sigmoidf_(perm_logit[3]);
        const float p1 = sigmoidf_(perm_logit[4]);
        const float p2 = sigmoidf_(perm_logit[5]);
        const u64 p02 = dup2(p0), q02 = dup2(1.0f - p0);
        const u64 p12 = dup2(p1), q12 = dup2(1.0f - p1);
        const u64 p22 = dup2(p2), q22 = dup2(1.0f - p2);

        tr_s2c_p(vc, sp, lane);           // contiguous for small perms
        perm_small_p<4 >(vc, q02, p02, q12, p12, q22, p22);
        perm_small_p<8 >(vc, q02, p02, q12, p12, q22, p22);
        perm_small_p<16>(vc, q02, p02, q12, p12, q22, p22);
        perm_small_p<32>(vc, q02, p02, q12, p12, q22, p22);
        perm_large_p<64,   true >(vc, sp, lane, q02, p02, q12, p12, q22, p22);
        perm_large_p<128,  false>(vc, sp, lane, q02, p02, q12, p12, q22, p22);
        perm_large_p<256,  false>(vc, sp, lane, q02, p02, q12, p12, q22, p22);
        perm_large_p<512,  false>(vc, sp, lane, q02, p02, q12, p12, q22, p22);
        perm_large_p<1024, false>(vc, sp, lane, q02, p02, q12, p12, q22, p22);
        tr_s2c_p(vc, sp, lane);           // contiguous for small diags

        diag_small_p<2 >(vc, sdup[1] + 0);
        diag_small_p<4 >(vc, sdup[1] + 1);
        diag_small_p<8 >(vc, sdup[1] + 3);
        diag_small_p<16>(vc, sdup[1] + 7);
        diag_small_p<32>(vc, sdup[1] + 15);
        tr_c2s_p(vc, sp, lane);           // strided for large diags
        diag_large_g<64  >(vc, g_AB[1] + 0,   g_CD[1] + 0,   lane);
        diag_large_g<128 >(vc, g_AB[1] + 32,  g_CD[1] + 32,  lane);
        diag_large_g<256 >(vc, g_AB[1] + 96,  g_CD[1] + 96,  lane);
        diag_large_g<512 >(vc, g_AB[1] + 224, g_CD[1] + 224, lane);
        diag_large_g<1024>(vc, g_AB[1] + 480, g_CD[1] + 480, lane);
    }

    // ---- writeback: stage real parts in smem (mod-4 skew), then float4 STG ---
    // skew4(i) = i + 4*(i>>5): keeps 32-blocks contiguous & 16B-aligned,
    // shifts blocks by 16B for conflict-free strided stores.
    __syncwarp();
#pragma unroll
    for (int j = 0; j < 32; ++j) {
        int a = (lane + 32 * j) + 4 * j;          // skew4(lane + 32*j)
        srf[a] = upk2(vc[j]).x;
    }
    __syncwarp();
    float* orow = out + (size_t)row * NN;
#pragma unroll
    for (int it = 0; it < 8; ++it) {
        int p = it * 128 + lane * 4;
        int a = p + 4 * (p >> 5);                 // skew4(p), 16B-aligned
        float4 t = *reinterpret_cast<const float4*>(srf + a);
        float4 bb = *reinterpret_cast<const float4*>(bias + p);
        t.x += bb.x;  t.y += bb.y;  t.z += bb.z;  t.w += bb.w;
        *reinterpret_cast<float4*>(orow + p) = t;
    }
}

extern "C" void kernel_launch(void* const* d_in, const int* in_sizes, int n_in,
                              void* d_out, int out_size)
{
    const float* x    = (const float*)d_in[0];
    const float* pl   = (const float*)d_in[1];
    const float* abcd = (const float*)d_in[2];
    const float* b    = (const float*)d_in[3];
    float* out = (float*)d_out;

    prep_kernel<<<16, 128>>>(abcd);        // repack large-diag coeffs (float4)

    int rows = in_sizes[0] / NN;           // 16384
    int ctas = rows / WPC;                 // 4096
    butterfly_kernel<<<ctas, WPC * 32>>>(x, pl, abcd, b, out);
}

// round 14
// speedup vs baseline: 1.1088x; 1.1088x over previous
#include <cuda_runtime.h>

#define NN        1024
#define TOTAL_AB  4092
#define WPC       4                 // warps (rows) per CTA
#define ROWPAD    (NN + (NN >> 5))  // skewed plane size (1056 elements)

typedef unsigned long long u64;

__device__ __forceinline__ int skew(int i) { return i + (i >> 5); }
__device__ __forceinline__ float sigmoidf_(float z) { return 1.0f / (1.0f + expf(-z)); }

// ===================== f32x2 packed helpers (PTX-only) =======================
__device__ __forceinline__ u64 pk2(float x, float y) {
    u64 r; asm("mov.b64 %0,{%1,%2};" : "=l"(r) : "f"(x), "f"(y)); return r;
}
__device__ __forceinline__ float2 upk2(u64 v) {
    float2 r; asm("mov.b64 {%0,%1},%2;" : "=f"(r.x), "=f"(r.y) : "l"(v)); return r;
}
__device__ __forceinline__ u64 dup2(float x) { return pk2(x, x); }
__device__ __forceinline__ u64 swp2(u64 v) {
    u64 r;
    asm("{.reg .f32 a,b; mov.b64 {a,b},%1; mov.b64 %0,{b,a};}" : "=l"(r) : "l"(v));
    return r;
}
__device__ __forceinline__ u64 fma2_(u64 a, u64 b, u64 c) {
    u64 d; asm("fma.rn.f32x2 %0,%1,%2,%3;" : "=l"(d) : "l"(a), "l"(b), "l"(c)); return d;
}
__device__ __forceinline__ u64 mul2_(u64 a, u64 b) {
    u64 d; asm("mul.rn.f32x2 %0,%1,%2;" : "=l"(d) : "l"(a), "l"(b)); return d;
}
__device__ __forceinline__ u64 lerp2(u64 q, u64 x, u64 p, u64 e) {
    return fma2_(q, x, mul2_(p, e));
}

// ====== repacked large-diag coefficient buffers (filled by prep kernel) ======
// pair-unit offsets within a depth: m=64:0, 128:32, 256:96, 512:224, 1024:480
__device__ float4 g_AB[2][992];
__device__ float4 g_CD[2][992];

__global__ void prep_kernel(const float* __restrict__ abcd_f) {
    int t = blockIdx.x * blockDim.x + threadIdx.x;
    if (t >= 2 * 992) return;
    int d = t / 992, r = t % 992;
    int m, k, off, po;
    if      (r < 32)  { m = 64;   k = r;       off = 3840; po = 0;   }
    else if (r < 96)  { m = 128;  k = r - 32;  off = 3584; po = 32;  }
    else if (r < 224) { m = 256;  k = r - 96;  off = 3072; po = 96;  }
    else if (r < 480) { m = 512;  k = r - 224; off = 2048; po = 224; }
    else              { m = 1024; k = r - 480; off = 0;    po = 480; }
    const float2* ab = reinterpret_cast<const float2*>(abcd_f) + d * TOTAL_AB + off;
    float2 A = ab[k], B = ab[m / 2 + k], C = ab[m + k], D = ab[m + m / 2 + k];
    g_AB[d][po + k] = make_float4(A.x, A.y, B.x, B.y);
    g_CD[d][po + k] = make_float4(C.x, C.y, D.x, D.y);
}

// ================= small (in-register) perm factor, REAL, M = 4..32 ==========
template<int M>
__device__ __forceinline__ void perm_small_r(float (&v)[32], float p0, float p1, float p2) {
    const float q0 = 1.0f - p0, q1 = 1.0f - p1, q2 = 1.0f - p2;
#pragma unroll
    for (int jb = 0; jb < 32; jb += M) {
        float todd[M / 2];
#pragma unroll
        for (int k = 0; k < M / 2; ++k) todd[k] = v[jb + 2 * k + 1];
#pragma unroll
        for (int k = 0; k < M / 2; ++k)
            v[jb + k] = q0 * v[jb + k] + p0 * v[jb + 2 * k];
#pragma unroll
        for (int k = 0; k < M / 2; ++k)
            v[jb + M / 2 + k] = q0 * v[jb + M / 2 + k] + p0 * todd[k];
#pragma unroll
        for (int k = 0; k < M / 4; ++k) {
            int a = jb + k, b = jb + M / 2 - 1 - k;
            float va = v[a], vb = v[b];
            v[a] = q1 * va + p1 * vb;  v[b] = q1 * vb + p1 * va;
            int c = jb + M / 2 + k, e = jb + M - 1 - k;
            float vc = v[c], ve = v[e];
            v[c] = q2 * vc + p2 * ve;  v[e] = q2 * ve + p2 * vc;
        }
    }
}

// ============ small perm factor, COMPLEX packed (contiguous layout) ==========
template<int M>
__device__ __forceinline__ void perm_small_p(u64 (&v)[32], u64 q02, u64 p02,
                                             u64 q12, u64 p12, u64 q22, u64 p22) {
#pragma unroll
    for (int jb = 0; jb < 32; jb += M) {
        u64 todd[M / 2];
#pragma unroll
        for (int k = 0; k < M / 2; ++k) todd[k] = v[jb + 2 * k + 1];
#pragma unroll
        for (int k = 0; k < M / 2; ++k)
            v[jb + k] = lerp2(q02, v[jb + k], p02, v[jb + 2 * k]);
#pragma unroll
        for (int k = 0; k < M / 2; ++k)
            v[jb + M / 2 + k] = lerp2(q02, v[jb + M / 2 + k], p02, todd[k]);
#pragma unroll
        for (int k = 0; k < M / 4; ++k) {
            int a = jb + k, b = jb + M / 2 - 1 - k;
            u64 va = v[a], vb = v[b];
            v[a] = lerp2(q12, va, p12, vb);
            v[b] = lerp2(q12, vb, p12, va);
            int c = jb + M / 2 + k, e = jb + M - 1 - k;
            u64 vc = v[c], ve = v[e];
            v[c] = lerp2(q22, vc, p22, ve);
            v[e] = lerp2(q22, ve, p22, vc);
        }
    }
}

// ============ large perm factor, REAL, strided layout (lane + 32*j) ==========
template<int M, bool FIRST>
__device__ __forceinline__ void perm_large_r(float (&v)[32], float* __restrict__ sr,
                                             int lane, float p0, float p1, float p2) {
    constexpr int M32 = M / 32, H32 = M / 64;
    const float q0 = 1.0f - p0;
    __syncwarp();
    if (FIRST) {
#pragma unroll
        for (int j = 0; j < 32; ++j) sr[skew(32 * lane + j)] = v[j];
    } else {
#pragma unroll
        for (int j = 0; j < 32; ++j) sr[skew(lane + 32 * j)] = v[j];
    }
    __syncwarp();
#pragma unroll
    for (int j = 0; j < 32; ++j) {
        int jm = j & (M32 - 1);
        bool hieo = jm >= H32;
        int i = lane + 32 * j;
        int q = i & (M - 1);
        int src = i + q - (hieo ? (M - 1) : 0);
        float xi = FIRST ? sr[skew(i)] : v[j];
        v[j] = q0 * xi + p0 * sr[skew(src)];
    }
    const int rl = 31 - lane;
#pragma unroll
    for (int j = 0; j < 32; ++j) {
        int jm = j & (M32 - 1);
        bool hi = jm >= H32;
        int j2 = j - 2 * jm + (hi ? 2 * H32 : 0) + H32 - 1;
        float pp = hi ? p2 : p1;
        float qq = 1.0f - pp;
        if (j2 == j) {
            float a = __shfl_sync(0xffffffffu, v[j], rl);
            v[j] = qq * v[j] + pp * a;
        } else if (j2 > j) {
            float a = __shfl_sync(0xffffffffu, v[j2], rl);
            float b = __shfl_sync(0xffffffffu, v[j],  rl);
            v[j]  = qq * v[j]  + pp * a;
            v[j2] = qq * v[j2] + pp * b;
        }
    }
}

// ===== large perm factor, COMPLEX packed, strided layout, SoA float planes ===
// eo pass uses two float half-planes (rpl/ipl) so the stride-2 gathers are
// bank-conflict-free (float bank-stride 2 covers all banks per half-warp),
// unlike the u64 form (bank-stride 4 -> 2-way conflict).
template<int M, bool FIRST>
__device__ __forceinline__ void perm_large_p(u64 (&v)[32],
                                             float* __restrict__ rpl,
                                             float* __restrict__ ipl, int lane,
                                             u64 q02, u64 p02, u64 q12, u64 p12,
                                             u64 q22, u64 p22) {
    constexpr int M32 = M / 32, H32 = M / 64;
    __syncwarp();
#pragma unroll
    for (int j = 0; j < 32; ++j) {
        int idx = FIRST ? (32 * lane + j) : (lane + 32 * j);
        int a = skew(idx);
        float2 t = upk2(v[j]);
        rpl[a] = t.x;
        ipl[a] = t.y;
    }
    __syncwarp();
#pragma unroll
    for (int j = 0; j < 32; ++j) {
        int jm = j & (M32 - 1);
        bool hieo = jm >= H32;
        int i = lane + 32 * j;
        int q = i & (M - 1);
        int src = i + q - (hieo ? (M - 1) : 0);
        int sa = skew(src);
        u64 e = pk2(rpl[sa], ipl[sa]);
        u64 x;
        if (FIRST) { int ia = skew(i); x = pk2(rpl[ia], ipl[ia]); }
        else       { x = v[j]; }
        v[j] = lerp2(q02, x, p02, e);
    }
    const int rl = 31 - lane;
#pragma unroll
    for (int j = 0; j < 32; ++j) {
        int jm = j & (M32 - 1);
        bool hi = jm >= H32;
        int j2 = j - 2 * jm + (hi ? 2 * H32 : 0) + H32 - 1;
        u64 pp2 = hi ? p22 : p12;
        u64 qq2 = hi ? q22 : q12;
        if (j2 == j) {
            u64 a = __shfl_sync(0xffffffffu, v[j], rl);
            v[j] = lerp2(qq2, v[j], pp2, a);
        } else if (j2 > j) {
            u64 a = __shfl_sync(0xffffffffu, v[j2], rl);
            u64 b = __shfl_sync(0xffffffffu, v[j],  rl);
            v[j]  = lerp2(qq2, v[j],  pp2, a);
            v[j2] = lerp2(qq2, v[j2], pp2, b);
        }
    }
}

// ====== small diag, COMPLEX packed, contiguous; coeffs via LDS.128 ===========
// dup[k][8] = {(Ax,Ax),(-Ay,Ay),(Bx,Bx),(-By,By),(Cx,Cx),(-Cy,Cy),(Dx,Dx),(-Dy,Dy)}
template<int M>
__device__ __forceinline__ void diag_small_p(u64 (&v)[32], const u64 (*__restrict__ dup)[8]) {
#pragma unroll
    for (int k = 0; k < M / 2; ++k) {
        const ulonglong2* __restrict__ q = reinterpret_cast<const ulonglong2*>(dup[k]);
        const ulonglong2 t0 = q[0], t1 = q[1], t2 = q[2], t3 = q[3];
        const u64 Ax = t0.x, Ay = t0.y, Bx = t1.x, By = t1.y;
        const u64 Cx = t2.x, Cy = t2.y, Dx = t3.x, Dy = t3.y;
#pragma unroll
        for (int jb = 0; jb < 32; jb += M) {
            u64 x1 = v[jb + k], x2 = v[jb + k + M / 2];
            u64 x1s = swp2(x1), x2s = swp2(x2);
            v[jb + k]         = fma2_(Ax, x1, fma2_(Ay, x1s, fma2_(Bx, x2, mul2_(By, x2s))));
            v[jb + k + M / 2] = fma2_(Cx, x1, fma2_(Cy, x1s, fma2_(Dx, x2, mul2_(Dy, x2s))));
        }
    }
}

// ====== large diag, strided layout, repacked float4 coeffs (2x LDG.128) ======
template<int M>
__device__ __forceinline__ void diag_large_g(u64 (&v)[32],
                                             const float4* __restrict__ gab,
                                             const float4* __restrict__ gcd, int lane) {
    constexpr int M32 = M / 32, H32 = M / 64;
#pragma unroll
    for (int j = 0; j < 32; ++j) {
        int jm = j & (M32 - 1);
        if (jm < H32) {
            int j2 = j + H32;
            int k = lane + 32 * jm;            // consecutive across lanes
            float4 AB = gab[k];
            float4 CD = gcd[k];
            float2 x1 = upk2(v[j]), x2 = upk2(v[j2]);
            float yr1 = AB.x * x1.x - AB.y * x1.y + AB.z * x2.x - AB.w * x2.y;
            float yi1 = AB.x * x1.y + AB.y * x1.x + AB.z * x2.y + AB.w * x2.x;
            float yr2 = CD.x * x1.x - CD.y * x1.y + CD.z * x2.x - CD.w * x2.y;
            float yi2 = CD.x * x1.y + CD.y * x1.x + CD.z * x2.y + CD.w * x2.x;
            v[j]  = pk2(yr1, yi1);
            v[j2] = pk2(yr2, yi2);
        }
    }
}

// ============================ layout transposes ==============================
__device__ __forceinline__ void tr_s2c_r(float (&v)[32], float* __restrict__ sr, int lane) {
    __syncwarp();
#pragma unroll
    for (int j = 0; j < 32; ++j) sr[skew(lane + 32 * j)] = v[j];
    __syncwarp();
#pragma unroll
    for (int j = 0; j < 32; ++j) v[j] = sr[skew(32 * lane + j)];
}
__device__ __forceinline__ void tr_s2c_p(u64 (&v)[32], u64* __restrict__ sp, int lane) {
    __syncwarp();
#pragma unroll
    for (int j = 0; j < 32; ++j) sp[skew(lane + 32 * j)] = v[j];
    __syncwarp();
#pragma unroll
    for (int j = 0; j < 32; ++j) v[j] = sp[skew(32 * lane + j)];
}
__device__ __forceinline__ void tr_c2s_p(u64 (&v)[32], u64* __restrict__ sp, int lane) {
    __syncwarp();
#pragma unroll
    for (int j = 0; j < 32; ++j) sp[skew(32 * lane + j)] = v[j];
    __syncwarp();
#pragma unroll
    for (int j = 0; j < 32; ++j) v[j] = sp[skew(lane + 32 * j)];
}

__global__ void __launch_bounds__(WPC * 32, 3)
butterfly_kernel(const float* __restrict__ x,
                 const float* __restrict__ perm_logit,
                 const float* __restrict__ abcd_f,
                 const float* __restrict__ bias,
                 float* __restrict__ out)
{
    __shared__ u64 splane[WPC][ROWPAD];                 // 33.8 KB per-warp row plane
    __shared__ __align__(16) u64 sdup[2][31][8];        // 3.9 KB packed small-diag coeffs

    const int warp = threadIdx.x >> 5;
    const int lane = threadIdx.x & 31;
    const int row  = blockIdx.x * WPC + warp;
    u64*   sp  = splane[warp];
    float* srf = reinterpret_cast<float*>(sp);          // float view (2112 slots/warp)
    float* rpl = srf;                                   // SoA real half-plane
    float* ipl = srf + ROWPAD;                          // SoA imag half-plane

    const float2* abcd = reinterpret_cast<const float2*>(abcd_f);

    // ---- build packed coefficient table for small diags (both depths) ----
    for (int t = threadIdx.x; t < 62; t += blockDim.x) {
        int d = t / 31, s = t % 31;
        int M, k, fac;
        if      (s < 1)  { M = 2;  k = s;      fac = 4088; }
        else if (s < 3)  { M = 4;  k = s - 1;  fac = 4080; }
        else if (s < 7)  { M = 8;  k = s - 3;  fac = 4064; }
        else if (s < 15) { M = 16; k = s - 7;  fac = 4032; }
        else             { M = 32; k = s - 15; fac = 3968; }
        const float2* ab = abcd + d * TOTAL_AB + fac;
        float2 A = ab[k], B = ab[M / 2 + k], C = ab[M + k], D = ab[M + M / 2 + k];
        ulonglong2* o = reinterpret_cast<ulonglong2*>(sdup[d][s]);
        o[0] = make_ulonglong2(dup2(A.x), pk2(-A.y, A.y));
        o[1] = make_ulonglong2(dup2(B.x), pk2(-B.y, B.y));
        o[2] = make_ulonglong2(dup2(C.x), pk2(-C.y, C.y));
        o[3] = make_ulonglong2(dup2(D.x), pk2(-D.y, D.y));
    }
    __syncthreads();

    // ---- coalesced load of the row (real) into smem, pick up contiguous chunk ----
    const float* xr = x + (size_t)row * NN;
#pragma unroll
    for (int it = 0; it < 8; ++it) {
        int p = it * 128 + lane * 4;
        float4 t = *reinterpret_cast<const float4*>(xr + p);
        srf[skew(p + 0)] = t.x;
        srf[skew(p + 1)] = t.y;
        srf[skew(p + 2)] = t.z;
        srf[skew(p + 3)] = t.w;
    }
    __syncwarp();
    float vr[32];
#pragma unroll
    for (int j = 0; j < 32; ++j) vr[j] = srf[skew(lane * 32 + j)];

    // ======================= depth 0: perms are purely REAL ===================
    {
        const float p0 = sigmoidf_(perm_logit[0]);
        const float p1 = sigmoidf_(perm_logit[1]);
        const float p2 = sigmoidf_(perm_logit[2]);
        perm_small_r<4 >(vr, p0, p1, p2);
        perm_small_r<8 >(vr, p0, p1, p2);
        perm_small_r<16>(vr, p0, p1, p2);
        perm_small_r<32>(vr, p0, p1, p2);
        perm_large_r<64,   true >(vr, srf, lane, p0, p1, p2);
        perm_large_r<128,  false>(vr, srf, lane, p0, p1, p2);
        perm_large_r<256,  false>(vr, srf, lane, p0, p1, p2);
        perm_large_r<512,  false>(vr, srf, lane, p0, p1, p2);
        perm_large_r<1024, false>(vr, srf, lane, p0, p1, p2);
        tr_s2c_r(vr, srf, lane);   // back to contiguous for diags
    }

    // ---- first diag (m=2) with imag==0 input: real -> packed complex ----
    u64 vc[32];
    {
        const u64* abq = reinterpret_cast<const u64*>(abcd + 4088);
        const u64 A = abq[0], B = abq[1], C = abq[2], D = abq[3];
#pragma unroll
        for (int jb = 0; jb < 32; jb += 2) {
            u64 x1 = dup2(vr[jb]), x2 = dup2(vr[jb + 1]);
            vc[jb]     = fma2_(A, x1, mul2_(B, x2));
            vc[jb + 1] = fma2_(C, x1, mul2_(D, x2));
        }
    }
    diag_small_p<4 >(vc, sdup[0] + 1);
    diag_small_p<8 >(vc, sdup[0] + 3);
    diag_small_p<16>(vc, sdup[0] + 7);
    diag_small_p<32>(vc, sdup[0] + 15);
    tr_c2s_p(vc, sp, lane);               // strided for large diags
    diag_large_g<64  >(vc, g_AB[0] + 0,   g_CD[0] + 0,   lane);
    diag_large_g<128 >(vc, g_AB[0] + 32,  g_CD[0] + 32,  lane);
    diag_large_g<256 >(vc, g_AB[0] + 96,  g_CD[0] + 96,  lane);
    diag_large_g<512 >(vc, g_AB[0] + 224, g_CD[0] + 224, lane);
    diag_large_g<1024>(vc, g_AB[0] + 480, g_CD[0] + 480, lane);

    // ======================= depth 1: full packed complex =====================
    {
        const float p0 = sigmoidf_(perm_logit[3]);
        const float p1 = sigmoidf_(perm_logit[4]);
        const float p2 = sigmoidf_(perm_logit[5]);
        const u64 p02 = dup2(p0), q02 = dup2(1.0f - p0);
        const u64 p12 = dup2(p1), q12 = dup2(1.0f - p1);
        const u64 p22 = dup2(p2), q22 = dup2(1.0f - p2);

        tr_s2c_p(vc, sp, lane);           // contiguous for small perms
        perm_small_p<4 >(vc, q02, p02, q12, p12, q22, p22);
        perm_small_p<8 >(vc, q02, p02, q12, p12, q22, p22);
        perm_small_p<16>(vc, q02, p02, q12, p12, q22, p22);
        perm_small_p<32>(vc, q02, p02, q12, p12, q22, p22);
        perm_large_p<64,   true >(vc, rpl, ipl, lane, q02, p02, q12, p12, q22, p22);
        perm_large_p<128,  false>(vc, rpl, ipl, lane, q02, p02, q12, p12, q22, p22);
        perm_large_p<256,  false>(vc, rpl, ipl, lane, q02, p02, q12, p12, q22, p22);
        perm_large_p<512,  false>(vc, rpl, ipl, lane, q02, p02, q12, p12, q22, p22);
        perm_large_p<1024, false>(vc, rpl, ipl, lane, q02, p02, q12, p12, q22, p22);
        tr_s2c_p(vc, sp, lane);           // contiguous for small diags

        diag_small_p<2 >(vc, sdup[1] + 0);
        diag_small_p<4 >(vc, sdup[1] + 1);
        diag_small_p<8 >(vc, sdup[1] + 3);
        diag_small_p<16>(vc, sdup[1] + 7);
        diag_small_p<32>(vc, sdup[1] + 15);
        tr_c2s_p(vc, sp, lane);           // strided for large diags
        diag_large_g<64  >(vc, g_AB[1] + 0,   g_CD[1] + 0,   lane);
        diag_large_g<128 >(vc, g_AB[1] + 32,  g_CD[1] + 32,  lane);
        diag_large_g<256 >(vc, g_AB[1] + 96,  g_CD[1] + 96,  lane);
        diag_large_g<512 >(vc, g_AB[1] + 224, g_CD[1] + 224, lane);
        diag_large_g<1024>(vc, g_AB[1] + 480, g_CD[1] + 480, lane);
    }

    // ---- write back: strided layout is already coalesced across lanes ----
    float* orow = out + (size_t)row * NN;
#pragma unroll
    for (int j = 0; j < 32; ++j) {
        int p = lane + 32 * j;
        orow[p] = upk2(vc[j]).x + bias[p];
    }
}

extern "C" void kernel_launch(void* const* d_in, const int* in_sizes, int n_in,
                              void* d_out, int out_size)
{
    const float* x    = (const float*)d_in[0];
    const float* pl   = (const float*)d_in[1];
    const float* abcd = (const float*)d_in[2];
    const float* b    = (const float*)d_in[3];
    float* out = (float*)d_out;

    prep_kernel<<<16, 128>>>(abcd);        // repack large-diag coeffs (float4)

    int rows = in_sizes[0] / NN;           // 16384
    int ctas = rows / WPC;                 // 4096
    butterfly_kernel<<<ctas, WPC * 32>>>(x, pl, abcd, b, out);
}